// round 1
// baseline (speedup 1.0000x reference)
#include <cuda_runtime.h>
#include <cuda_bf16.h>
#include <cstdint>

// ---------------------------------------------------------------------------
// Problem constants
// ---------------------------------------------------------------------------
#define BATCH   64
#define SEQ     2048
#define CIN     32
#define WIN     20
#define DIN     (WIN * CIN)      // 640
#define DP      (DIN / 2)        // 320
#define HID     128
#define G4      (4 * HID)        // 512
#define L_OUT   (SEQ - WIN)      // 2028
#define LBL     48

// ---------------------------------------------------------------------------
// Scratch (static __device__ arrays; no cudaMalloc allowed)
// ---------------------------------------------------------------------------
__device__ float g_wc[DIN * G4];                       // combined proj->ih0 weight [d][g]
__device__ float g_bias0[G4];
__device__ float g_xpre[(size_t)BATCH * L_OUT * G4];   // per-step gate preactivations
__device__ float g_hseq[(size_t)BATCH * L_OUT * HID];  // per-step hidden outputs

// ---------------------------------------------------------------------------
// Packed fp32x2 helpers (Blackwell f32x2 pipe: 2x FFMA throughput vs 3-reg FFMA)
// ---------------------------------------------------------------------------
__device__ __forceinline__ unsigned long long pk2(float x, float y) {
    unsigned long long r;
    asm("mov.b64 %0, {%1, %2};" : "=l"(r) : "f"(x), "f"(y));
    return r;
}
__device__ __forceinline__ float2 unpk2(unsigned long long v) {
    float2 r;
    asm("mov.b64 {%0, %1}, %2;" : "=f"(r.x), "=f"(r.y) : "l"(v));
    return r;
}
__device__ __forceinline__ void fma2(unsigned long long& d, unsigned long long a,
                                     unsigned long long b) {
    asm("fma.rn.f32x2 %0, %1, %2, %3;" : "=l"(d) : "l"(a), "l"(b), "l"(d));
}

// ---------------------------------------------------------------------------
// Cluster / mbarrier helpers
// ---------------------------------------------------------------------------
__device__ __forceinline__ unsigned smem_u32(const void* p) {
    return (unsigned)__cvta_generic_to_shared(p);
}
__device__ __forceinline__ unsigned mapa_rank(unsigned addr, unsigned rank) {
    unsigned r;
    asm("mapa.shared::cluster.u32 %0, %1, %2;" : "=r"(r) : "r"(addr), "r"(rank));
    return r;
}
__device__ __forceinline__ void st_cluster_f32(unsigned addr, float v) {
    asm volatile("st.shared::cluster.f32 [%0], %1;" :: "r"(addr), "f"(v) : "memory");
}
__device__ __forceinline__ void mbar_init(unsigned addr, unsigned cnt) {
    asm volatile("mbarrier.init.shared.b64 [%0], %1;" :: "r"(addr), "r"(cnt) : "memory");
}
__device__ __forceinline__ void mbar_arrive_remote(unsigned addr) {
    asm volatile("mbarrier.arrive.release.cluster.shared::cluster.b64 _, [%0];"
                 :: "r"(addr) : "memory");
}
__device__ __forceinline__ void mbar_wait_cluster(unsigned addr, unsigned parity) {
    asm volatile(
        "{\n\t"
        ".reg .pred P1;\n\t"
        "WAIT_%=:\n\t"
        "mbarrier.try_wait.parity.acquire.cluster.shared::cta.b64 P1, [%0], %1, 0x989680;\n\t"
        "@P1 bra.uni DONE_%=;\n\t"
        "bra.uni WAIT_%=;\n\t"
        "DONE_%=:\n\t"
        "}"
        :: "r"(addr), "r"(parity) : "memory");
}
__device__ __forceinline__ void cluster_barrier() {
    asm volatile("barrier.cluster.arrive.aligned;" ::: "memory");
    asm volatile("barrier.cluster.wait.aligned;" ::: "memory");
}

// ---------------------------------------------------------------------------
// Fast activations (fp32, ~1e-6 rel error; safe at extremes)
// ---------------------------------------------------------------------------
__device__ __forceinline__ float fast_sigmoid(float x) {
    return 1.f / (1.f + __expf(-x));
}
__device__ __forceinline__ float fast_tanh(float x) {
    float ax = fabsf(x);
    float e  = __expf(-2.f * ax);
    float r  = __fdividef(1.f - e, 1.f + e);
    return copysignf(r, x);
}

// ---------------------------------------------------------------------------
// Kernel 1: fold projection into layer-0 input weight.
// Wc[d][g] = sum_p proj_w[p][d] * w_ih0[g][p]   (640 x 512, K=320)
// ---------------------------------------------------------------------------
__global__ void combine_kernel(const float* __restrict__ proj_w,
                               const float* __restrict__ w_ih0) {
    __shared__ float sPW[32][32];   // [p][d]
    __shared__ float sWI[32][33];   // [g][p]
    int tx = threadIdx.x, ty = threadIdx.y;
    int d0 = blockIdx.x * 32, g0 = blockIdx.y * 32;
    float acc = 0.f;
    for (int p0 = 0; p0 < DP; p0 += 32) {
        sPW[ty][tx] = proj_w[(size_t)(p0 + ty) * DIN + d0 + tx];
        sWI[ty][tx] = w_ih0[(size_t)(g0 + ty) * DP + p0 + tx];
        __syncthreads();
#pragma unroll
        for (int p = 0; p < 32; p++) acc += sPW[p][tx] * sWI[ty][p];
        __syncthreads();
    }
    g_wc[(size_t)(d0 + tx) * G4 + g0 + ty] = acc;
}

// bias0[g] = b_ih0[g] + b_hh0[g] + sum_p proj_b[p] * w_ih0[g][p]
__global__ void bias0_kernel(const float* __restrict__ proj_b,
                             const float* __restrict__ w_ih0,
                             const float* __restrict__ b_ih0,
                             const float* __restrict__ b_hh0) {
    int gidx = threadIdx.x;
    float acc = b_ih0[gidx] + b_hh0[gidx];
    const float* wr = w_ih0 + (size_t)gidx * DP;
    for (int p = 0; p < DP; p++) acc += proj_b[p] * wr[p];
    g_bias0[gidx] = acc;
}

// ---------------------------------------------------------------------------
// Kernel 2: layer-0 preactivations (implicit sliding-window GEMM).
// xpre0[b][t][g] = bias0[g] + sum_{d<640} inputs_flat[b][t*32 + d] * Wc[d][g]
// Block: BM=128 t-rows, BN=64 g-cols, 256 threads (tx: 16 n-groups of 4,
// ty: 16 m-groups of 8). A-panel is a contiguous slice -> one SMEM load.
// ---------------------------------------------------------------------------
__global__ void __launch_bounds__(256)
xpre0_kernel(const float* __restrict__ in) {
    __shared__ __align__(16) float sIn[128 * 32 + DIN];     // 4736 floats
    __shared__ __align__(16) float sB[32][64];

    int tid = threadIdx.x;
    int tx = tid & 15, ty = tid >> 4;
    int t0 = blockIdx.x * 128;
    int n0 = blockIdx.y * 64;
    int b  = blockIdx.z;

    const float* inb = in + (size_t)b * SEQ * CIN;
    int base = t0 * CIN;
    for (int i = tid; i < 128 * 32 + DIN; i += 256) {
        int gi = base + i;
        sIn[i] = (gi < SEQ * CIN) ? inb[gi] : 0.f;
    }
    __syncthreads();

    unsigned long long acc[8][2];
#pragma unroll
    for (int i = 0; i < 8; i++) { acc[i][0] = pk2(0.f, 0.f); acc[i][1] = pk2(0.f, 0.f); }

    for (int k0 = 0; k0 < DIN; k0 += 32) {
#pragma unroll
        for (int r = 0; r < 2; r++) {
            int j = tid * 8 + r * 4;
            int kk = j >> 6, nn = j & 63;
            *(float4*)&sB[kk][nn] =
                *(const float4*)&g_wc[(size_t)(k0 + kk) * G4 + n0 + nn];
        }
        __syncthreads();
#pragma unroll
        for (int k = 0; k < 32; k++) {
            ulonglong2 bb = *(const ulonglong2*)&sB[k][tx * 4];
#pragma unroll
            for (int i = 0; i < 8; i++) {
                float a = sIn[(ty * 8 + i) * CIN + k0 + k];
                unsigned long long aa = pk2(a, a);
                fma2(acc[i][0], aa, bb.x);
                fma2(acc[i][1], aa, bb.y);
            }
        }
        __syncthreads();
    }

    float4 bias = *(const float4*)&g_bias0[n0 + tx * 4];
#pragma unroll
    for (int i = 0; i < 8; i++) {
        int t = t0 + ty * 8 + i;
        if (t < L_OUT) {
            float2 p0 = unpk2(acc[i][0]);
            float2 p1 = unpk2(acc[i][1]);
            float4 v = make_float4(p0.x + bias.x, p0.y + bias.y,
                                   p1.x + bias.z, p1.y + bias.w);
            *(float4*)&g_xpre[((size_t)b * L_OUT + t) * G4 + n0 + tx * 4] = v;
        }
    }
}

// ---------------------------------------------------------------------------
// Kernel 3: input preactivations for layers 1..3.
// xpre[b][t][g] = b_ih[g] + b_hh[g] + sum_j hseq[b][t][j] * w_ih[g][j]
// BM=64, BN=64, K=128 in two 64-wide tiles.
// ---------------------------------------------------------------------------
__global__ void __launch_bounds__(256)
gemm_ih_kernel(const float* __restrict__ w_ih,
               const float* __restrict__ b_ih,
               const float* __restrict__ b_hh) {
    __shared__ __align__(16) float sA[64 * 64];    // [m][k]
    __shared__ __align__(16) float sB[64 * 68];    // [k][n] padded

    int tid = threadIdx.x;
    int tx = tid & 15, ty = tid >> 4;
    int t0 = blockIdx.x * 64;
    int n0 = blockIdx.y * 64;
    int b  = blockIdx.z;

    unsigned long long acc[4][2];
#pragma unroll
    for (int i = 0; i < 4; i++) { acc[i][0] = pk2(0.f, 0.f); acc[i][1] = pk2(0.f, 0.f); }

    for (int kt = 0; kt < 2; kt++) {
#pragma unroll
        for (int r = 0; r < 4; r++) {
            int j = tid * 16 + r * 4;
            int row = j >> 6, col = j & 63;
            int t = t0 + row;
            float4 v = make_float4(0.f, 0.f, 0.f, 0.f);
            if (t < L_OUT)
                v = *(const float4*)&g_hseq[((size_t)b * L_OUT + t) * HID + kt * 64 + col];
            *(float4*)&sA[row * 64 + col] = v;
        }
        for (int j = tid; j < 64 * 64; j += 256) {
            int n = j >> 6, kk = j & 63;
            sB[kk * 68 + n] = w_ih[(size_t)(n0 + n) * HID + kt * 64 + kk];
        }
        __syncthreads();
#pragma unroll
        for (int k = 0; k < 64; k++) {
            ulonglong2 bb = *(const ulonglong2*)&sB[k * 68 + tx * 4];
#pragma unroll
            for (int i = 0; i < 4; i++) {
                float a = sA[(ty * 4 + i) * 64 + k];
                unsigned long long aa = pk2(a, a);
                fma2(acc[i][0], aa, bb.x);
                fma2(acc[i][1], aa, bb.y);
            }
        }
        __syncthreads();
    }

    int n = n0 + tx * 4;
    float4 bias = make_float4(b_ih[n] + b_hh[n], b_ih[n + 1] + b_hh[n + 1],
                              b_ih[n + 2] + b_hh[n + 2], b_ih[n + 3] + b_hh[n + 3]);
#pragma unroll
    for (int i = 0; i < 4; i++) {
        int t = t0 + ty * 4 + i;
        if (t < L_OUT) {
            float2 p0 = unpk2(acc[i][0]);
            float2 p1 = unpk2(acc[i][1]);
            float4 v = make_float4(p0.x + bias.x, p0.y + bias.y,
                                   p1.x + bias.z, p1.y + bias.w);
            *(float4*)&g_xpre[((size_t)b * L_OUT + t) * G4 + n] = v;
        }
    }
}

// ---------------------------------------------------------------------------
// Kernel 4: recurrent scan. One batch element per 2-CTA cluster.
// Rank 0 owns gate rows [0,256) (i,f), rank 1 owns [256,512) (g,o).
// Each thread keeps its 128 recurrent weights in registers (f32x2 pairs).
// Symmetric DSMEM gate exchange; both ranks redundantly compute c,h
// (removes an h-broadcast hop from the serial critical path).
// ---------------------------------------------------------------------------
__global__ void __cluster_dims__(2, 1, 1) __launch_bounds__(256, 1)
scan_kernel(const float* __restrict__ w_hh, int write_hseq_unused) {
    __shared__ float h_sh[HID];
    __shared__ float gl[HID];               // partner gate from own CTA (f or o)
    __shared__ float gr[2][256];            // remote gates, double buffered
    __shared__ __align__(8) unsigned long long mbar;

    int tid  = threadIdx.x;
    int rank = blockIdx.x & 1;
    int b    = blockIdx.x >> 1;
    int g    = rank * 256 + tid;

    // recurrent weight row -> registers as f32x2 pairs
    unsigned long long w2[64];
    const ulonglong2* wr = (const ulonglong2*)(w_hh + (size_t)g * HID);
#pragma unroll
    for (int k = 0; k < 32; k++) {
        ulonglong2 u = wr[k];
        w2[2 * k] = u.x;
        w2[2 * k + 1] = u.y;
    }

    if (tid < HID) h_sh[tid] = 0.f;
    unsigned bar_a = smem_u32(&mbar);
    if (tid == 0) mbar_init(bar_a, 256);
    __syncthreads();
    cluster_barrier();   // peer mbar init + h_sh visible cluster-wide

    unsigned peer = rank ^ 1;
    unsigned peer_gr0 = mapa_rank(smem_u32(&gr[0][tid]), peer);
    unsigned peer_gr1 = mapa_rank(smem_u32(&gr[1][tid]), peer);
    unsigned peer_bar = mapa_rank(bar_a, peer);

    float c = 0.f;
    unsigned ph = 0;
    const size_t xbase = (size_t)b * L_OUT;
    float xp = g_xpre[xbase * G4 + g];
    bool is_tanh_gate = (rank == 1) && (tid < HID);

    for (int t = 0; t < L_OUT; t++) {
        // prefetch next step's preactivation (hides DRAM latency behind the dot)
        float xp_n = (t + 1 < L_OUT) ? g_xpre[(xbase + t + 1) * G4 + g] : 0.f;

        // dot(w_row, h) via packed f32x2 FMAs
        unsigned long long acc0 = pk2(0.f, 0.f), acc1 = pk2(0.f, 0.f);
        const ulonglong2* h2 = (const ulonglong2*)h_sh;
#pragma unroll
        for (int k = 0; k < 32; k++) {
            ulonglong2 u = h2[k];
            fma2(acc0, w2[2 * k], u.x);
            fma2(acc1, w2[2 * k + 1], u.y);
        }
        float2 s0 = unpk2(acc0), s1 = unpk2(acc1);
        float pre = ((s0.x + s0.y) + (s1.x + s1.y)) + xp;

        float act = is_tanh_gate ? fast_tanh(pre) : fast_sigmoid(pre);

        // exchange: local partner slot + remote (peer) slot + release-arrive
        if (tid >= HID) gl[tid - HID] = act;
        st_cluster_f32((t & 1) ? peer_gr1 : peer_gr0, act);
        mbar_arrive_remote(peer_bar);
        __syncthreads();   // gl visible; h_sh reads of this step complete

        if (tid < HID) {
            mbar_wait_cluster(bar_a, ph);   // acquire: remote gates visible
            const float* grb = gr[t & 1];
            float iv, fv, gv, ov;
            if (rank == 0) { iv = act;       fv = gl[tid];
                             gv = grb[tid];  ov = grb[HID + tid]; }
            else           { gv = act;       ov = gl[tid];
                             iv = grb[tid];  fv = grb[HID + tid]; }
            c = fv * c + iv * gv;
            float h = ov * fast_tanh(c);
            h_sh[tid] = h;
            if (rank == 0)
                g_hseq[(xbase + t) * HID + tid] = h;
        }
        __syncthreads();   // h_sh(t) ready for next dot
        ph ^= 1;
        xp = xp_n;
    }
    cluster_barrier();
}

// ---------------------------------------------------------------------------
// Kernel 5: readout. out[b][j] = out_b[j] + sum_k h_final[b][k] * out_w[j][k]
// ---------------------------------------------------------------------------
__global__ void out_kernel(const float* __restrict__ out_w,
                           const float* __restrict__ out_b,
                           float* __restrict__ out) {
    __shared__ float h[HID];
    int b = blockIdx.x;
    if (threadIdx.x < HID)
        h[threadIdx.x] = g_hseq[((size_t)b * L_OUT + (L_OUT - 1)) * HID + threadIdx.x];
    __syncthreads();
    if (threadIdx.x < LBL) {
        float acc = out_b[threadIdx.x];
        const float* wr = out_w + (size_t)threadIdx.x * HID;
#pragma unroll 8
        for (int k = 0; k < HID; k++) acc += wr[k] * h[k];
        out[(size_t)b * LBL + threadIdx.x] = acc;
    }
}

// ---------------------------------------------------------------------------
// Launch
// ---------------------------------------------------------------------------
extern "C" void kernel_launch(void* const* d_in, const int* in_sizes, int n_in,
                              void* d_out, int out_size) {
    const float* inputs    = (const float*)d_in[0];
    const float* proj_w    = (const float*)d_in[4];
    const float* proj_b    = (const float*)d_in[5];
    const float* w_ih0     = (const float*)d_in[6];
    const float* w_hh0     = (const float*)d_in[7];
    const float* b_ih0     = (const float*)d_in[8];
    const float* b_hh0     = (const float*)d_in[9];
    const float* w_ih_rest = (const float*)d_in[10];
    const float* w_hh_rest = (const float*)d_in[11];
    const float* b_ih_rest = (const float*)d_in[12];
    const float* b_hh_rest = (const float*)d_in[13];
    const float* out_w     = (const float*)d_in[14];
    const float* out_b     = (const float*)d_in[15];
    float* out = (float*)d_out;

    // prep: fold projection into layer-0 input weight + bias
    combine_kernel<<<dim3(DIN / 32, G4 / 32), dim3(32, 32)>>>(proj_w, w_ih0);
    bias0_kernel<<<1, G4>>>(proj_b, w_ih0, b_ih0, b_hh0);

    // layer-0 preactivations (implicit window GEMM)
    xpre0_kernel<<<dim3((L_OUT + 127) / 128, G4 / 64, BATCH), 256>>>(inputs);

    // layer-0 scan
    scan_kernel<<<BATCH * 2, 256>>>(w_hh0, 0);

    // layers 1..3
    for (int l = 0; l < 3; l++) {
        gemm_ih_kernel<<<dim3((L_OUT + 63) / 64, G4 / 64, BATCH), 256>>>(
            w_ih_rest + (size_t)l * G4 * HID,
            b_ih_rest + (size_t)l * G4,
            b_hh_rest + (size_t)l * G4);
        scan_kernel<<<BATCH * 2, 256>>>(w_hh_rest + (size_t)l * G4 * HID, 0);
    }

    // readout of final hidden state
    out_kernel<<<BATCH, 128>>>(out_w, out_b, out);
}